// round 16
// baseline (speedup 1.0000x reference)
#include <cuda_runtime.h>
#include <math.h>

#define BB 16
#define TT 4096
#define DD 512
#define NLEV 3
#define NECH 8              // e-chunks in k_proj
#define TCH 64              // tokens per fused chunk
#define NCHK (TT/TCH)       // 64
#define CTXCH 8             // d-chunks in k_ctx
#define BIG_NEG (-1e30f)

typedef unsigned long long ull;

// one enc row = DD floats = 128 ulonglong2 (16B) elements
#define ROW_U2 ((DD * 4) / 16)
static_assert(ROW_U2 == 128, "row stride in ulonglong2 units must be 128");

__device__ __forceinline__ ull pk2(float lo, float hi) {
    ull r; asm("mov.b64 %0, {%1,%2};" : "=l"(r) : "f"(lo), "f"(hi)); return r;
}
__device__ __forceinline__ ull fma2(ull a, ull b, ull c) {
    ull d; asm("fma.rn.f32x2 %0, %1, %2, %3;" : "=l"(d) : "l"(a), "l"(b), "l"(c)); return d;
}
__device__ __forceinline__ ull add2(ull a, ull b) {
    ull d; asm("add.rn.f32x2 %0, %1, %2;" : "=l"(d) : "l"(a), "l"(b)); return d;
}
__device__ __forceinline__ float hsum2(ull v) {
    float x, y; asm("mov.b64 {%0,%1}, %2;" : "=f"(x), "=f"(y) : "l"(v)); return x + y;
}
__device__ __forceinline__ void upk2(ull v, float& x, float& y) {
    asm("mov.b64 {%0,%1}, %2;" : "=f"(x), "=f"(y) : "l"(v));
}
// online-softmax monoid combine
__device__ __forceinline__ void smx_comb(float& m, float& s, float m2, float s2) {
    float M = fmaxf(m, m2);
    s = s * __expf(m - M) + s2 * __expf(m2 - M);
    m = M;
}

// ---------------- device scratch (no allocations allowed) ----------------
__device__ __align__(16) float g_u_part[NECH][NLEV][BB][DD];
__device__ float g_c_part[NECH][NLEV][BB];
__device__ __align__(16) float g_u[NLEV][BB][DD];
__device__ float g_logit0[BB][TT];               // level-0 logits only (for att out)
__device__ float g_cm[NLEV][BB][NCHK];           // per-chunk normalizer (max incl boundaries)
__device__ float g_cs[NLEV][BB][NCHK];           // per-chunk sum rel. to g_cm
__device__ __align__(16) float g_pooled_part[NCHK][NLEV][BB][DD];  // locally-scaled
__device__ __align__(16) float g_pooled[NLEV][BB][DD];
__device__ float g_ctx_part[NLEV][CTXCH][BB][DD];

// ---------------- kernel 1: u_i = s_prev @ Vw[i], c_i = s_prev . Vb[i] ----
__global__ void k_proj(const float* __restrict__ s_prev,
                       const float* __restrict__ Vw,
                       const float* __restrict__ Vb) {
    int i  = blockIdx.y;
    int dt = blockIdx.x & 3;
    int ec = blockIdx.x >> 2;
    int d  = dt * 128 + threadIdx.x;
    int e0 = ec * 64;

    __shared__ float sp[BB][64];
    for (int idx = threadIdx.x; idx < BB * 64; idx += 128) {
        int b = idx >> 6, e = idx & 63;
        sp[b][e] = s_prev[b * DD + e0 + e];
    }
    __syncthreads();

    float acc[BB];
#pragma unroll
    for (int b = 0; b < BB; b++) acc[b] = 0.f;

    const float* wp = Vw + (size_t)i * DD * DD + (size_t)e0 * DD + d;
#pragma unroll 4
    for (int e = 0; e < 64; e++) {
        float w = wp[(size_t)e * DD];
#pragma unroll
        for (int b = 0; b < BB; b++) acc[b] = fmaf(sp[b][e], w, acc[b]);
    }
#pragma unroll
    for (int b = 0; b < BB; b++) g_u_part[ec][i][b][d] = acc[b];

    if (dt == 0 && threadIdx.x < BB) {
        int b = threadIdx.x;
        float c = 0.f;
        for (int e = 0; e < 64; e++) c = fmaf(sp[b][e], Vb[i * DD + e0 + e], c);
        g_c_part[ec][i][b] = c;
    }
}

// ---------------- kernel 2: fold u partials -------------------------------
__global__ void k_fold_u() {
    int idx = blockIdx.x * 256 + threadIdx.x;
    if (idx < NLEV * BB * DD) {
        float s = 0.f;
#pragma unroll
        for (int p = 0; p < NECH; p++) s += (&g_u_part[0][0][0][0])[p * NLEV * BB * DD + idx];
        (&g_u[0][0][0])[idx] = s;
    }
}

// ---------------- profiling-alignment no-op (keeps k_fused in ncu slot) ---
__global__ void k_nop() {}

// ---------------- kernel 3: FULLY FUSED single-pass over enc --------------
// grid (NCHK=64, B), 128 threads (4 warps). __launch_bounds__(128,6) caps
// regs ~85 for 6 blocks/SM. 6 fused accumulator chains per pair.
__global__ void __launch_bounds__(128, 6) k_fused(const float* __restrict__ enc,
                                                  const int* __restrict__ mask) {
    int b    = blockIdx.y;
    int chnk = blockIdx.x;
    int t0   = chnk * TCH;
    int tid  = threadIdx.x, warp = tid >> 5, lane = tid & 31;

    __shared__ float sd[NLEV][68];     // dots, s = t - t0 + 2 in [0,68)
    __shared__ float slog[NLEV][66];   // logits, s in [0,66)
    __shared__ float sM[NLEV];
    __shared__ ull   sw[NLEV][TCH];    // packed local weights

    // register-cache u slices: lane owns ulonglong2 indices {lane+32q}
    ulonglong2 v0[4], v1[4], v2[4];
    {
        const ulonglong2* u0 = (const ulonglong2*)&g_u[0][b][0];
        const ulonglong2* u1 = (const ulonglong2*)&g_u[1][b][0];
        const ulonglong2* u2 = (const ulonglong2*)&g_u[2][b][0];
#pragma unroll
        for (int q = 0; q < 4; q++) {
            v0[q] = u0[lane + 32 * q];
            v1[q] = u1[lane + 32 * q];
            v2[q] = u2[lane + 32 * q];
        }
    }

    const ulonglong2* e2 = (const ulonglong2*)(enc + (size_t)b * TT * DD);

    // ---- phase 1: dots (pairs; warp w covers t0+16w..t0+16w+15) ----
    int  extra_t  = 0;
    bool has_x    = false;
    if (warp == 0 && t0 > 0)       { has_x = true; extra_t = t0 - 2; }
    if (warp == 1 && t0 + TCH < TT){ has_x = true; extra_t = t0 + TCH; }
    int npair = 8 + (has_x ? 1 : 0);

    for (int it = 0; it < npair; it++) {
        int tp = (it < 8) ? (t0 + warp * 16 + 2 * it) : extra_t;
        const ulonglong2* r0 = e2 + (size_t)tp * ROW_U2 + lane;
        const ulonglong2* r1 = e2 + (size_t)(tp + 1) * ROW_U2 + lane;

        ulonglong2 h0[4], h1[4];
#pragma unroll
        for (int q = 0; q < 4; q++) h0[q] = r0[32 * q];
#pragma unroll
        for (int q = 0; q < 4; q++) h1[q] = r1[32 * q];

        // 6 fused accumulator chains: (token, level)
        ull P0 = 0, P1 = 0, P2 = 0, Q0 = 0, Q1 = 0, Q2 = 0;
#pragma unroll
        for (int q = 0; q < 4; q++) {
            P0 = fma2(h0[q].x, v0[q].x, P0); P0 = fma2(h0[q].y, v0[q].y, P0);
            P1 = fma2(h0[q].x, v1[q].x, P1); P1 = fma2(h0[q].y, v1[q].y, P1);
            P2 = fma2(h0[q].x, v2[q].x, P2); P2 = fma2(h0[q].y, v2[q].y, P2);
            Q0 = fma2(h1[q].x, v0[q].x, Q0); Q0 = fma2(h1[q].y, v0[q].y, Q0);
            Q1 = fma2(h1[q].x, v1[q].x, Q1); Q1 = fma2(h1[q].y, v1[q].y, Q1);
            Q2 = fma2(h1[q].x, v2[q].x, Q2); Q2 = fma2(h1[q].y, v2[q].y, Q2);
        }
        ull p0 = pk2(hsum2(P0), hsum2(Q0));
        ull p1 = pk2(hsum2(P1), hsum2(Q1));
        ull p2 = pk2(hsum2(P2), hsum2(Q2));

#pragma unroll
        for (int off = 16; off; off >>= 1) {
            p0 = add2(p0, __shfl_down_sync(0xFFFFFFFFu, p0, off));
            p1 = add2(p1, __shfl_down_sync(0xFFFFFFFFu, p1, off));
            p2 = add2(p2, __shfl_down_sync(0xFFFFFFFFu, p2, off));
        }
        if (lane == 0) {
            int s0 = tp - t0 + 2;
            float x, y;
            upk2(p0, x, y); sd[0][s0] = x; sd[0][s0 + 1] = y;
            upk2(p1, x, y); sd[1][s0] = x; sd[1][s0 + 1] = y;
            upk2(p2, x, y); sd[2][s0] = x; sd[2][s0 + 1] = y;
        }
    }
    __syncthreads();

    // ---- phase 2a: logits (s = 0..65, l = t0-2+s); store only level 0 ----
    const int* mp = mask + b * TT;
    for (int idx = tid; idx < NLEV * 66; idx += 128) {
        int i = idx / 66, s = idx % 66;
        int l = t0 - 2 + s;
        int L = TT - i;
        float v = BIG_NEG;
        if (l >= 0 && l < L) {
            float ws = sd[i][s];
            bool  mk = (mp[l] != 0);
            if (i >= 1) { ws += sd[i][s + 1]; mk = mk || (mp[l + 1] != 0); }
            if (i == 2) { ws += sd[i][s + 2]; mk = mk || (mp[l + 2] != 0); }
            if (!mk) {
                float cst = 0.f;
#pragma unroll
                for (int p = 0; p < NECH; p++) cst += g_c_part[p][i][b];
                v = ws * (1.f / (float)(i + 1)) + cst;
            }
        }
        slog[i][s] = v;
        if (i == 0 && s >= 2) g_logit0[b][l] = v;
    }
    __syncthreads();

    // ---- phase 2b: chunk normalizer + sum (warp i = level i) ----
    // m' = max over ALL 66 logits (boundaries included => all exp args <= 0);
    // s  = sum over the chunk's own 64 positions (s=2..65) rel. to m'.
    if (warp < NLEV) {
        float a  = slog[warp][2 + lane];
        float bv = slog[warp][34 + lane];
        float m  = fmaxf(a, bv);
        if (lane < 2) m = fmaxf(m, slog[warp][lane]);   // boundary positions
#pragma unroll
        for (int off = 16; off; off >>= 1)
            m = fmaxf(m, __shfl_xor_sync(0xFFFFFFFFu, m, off));
        float s = __expf(a - m) + __expf(bv - m);
#pragma unroll
        for (int off = 16; off; off >>= 1)
            s += __shfl_xor_sync(0xFFFFFFFFu, s, off);
        if (lane == 0) {
            sM[warp] = m;
            g_cm[warp][b][chnk] = m;
            g_cs[warp][b][chnk] = s;
        }
    }
    __syncthreads();

    // ---- phase 2c: local pooling weights (chunk-normalized; args <= 0) ----
    for (int idx = tid; idx < NLEV * TCH; idx += 128) {
        int i = idx / TCH, j = idx % TCH, s = j + 2;
        float M = sM[i];
        float w = __expf(slog[i][s] - M);
        if (i >= 1) w += __expf(slog[i][s - 1] - M);
        if (i == 2) w += __expf(slog[i][s - 2] - M);
        sw[i][j] = pk2(w, w);
    }
    __syncthreads();

    // ---- phase 3: re-stream the tile (L1/L2-hot) ----
    const ulonglong2* base = e2 + (size_t)t0 * ROW_U2 + tid;
    ull a0x = 0, a0y = 0, a1x = 0, a1y = 0, a2x = 0, a2y = 0;

#pragma unroll 16
    for (int j = 0; j < TCH; j++) {
        ulonglong2 h = base[(size_t)j * ROW_U2];
        ull w0 = sw[0][j], w1 = sw[1][j], w2 = sw[2][j];
        a0x = fma2(w0, h.x, a0x); a0y = fma2(w0, h.y, a0y);
        a1x = fma2(w1, h.x, a1x); a1y = fma2(w1, h.y, a1y);
        a2x = fma2(w2, h.x, a2x); a2y = fma2(w2, h.y, a2y);
    }
    ulonglong2 r0; r0.x = a0x; r0.y = a0y;
    ulonglong2 r1; r1.x = a1x; r1.y = a1y;
    ulonglong2 r2; r2.x = a2x; r2.y = a2y;
    ((ulonglong2*)&g_pooled_part[chnk][0][b][0])[tid] = r0;
    ((ulonglong2*)&g_pooled_part[chnk][1][b][0])[tid] = r1;
    ((ulonglong2*)&g_pooled_part[chnk][2][b][0])[tid] = r2;
}

// ---------------- kernel 4: att output (level 0) --------------------------
__global__ void k_attout(float* __restrict__ out_att) {
    int b = blockIdx.y;
    int l = blockIdx.x * 512 + threadIdx.x;
    int warp = threadIdx.x >> 5, lane = threadIdx.x & 31;

    __shared__ float sM, sI;
    if (warp == 0) {
        float m = g_cm[0][b][lane], s = g_cs[0][b][lane];
        smx_comb(m, s, g_cm[0][b][lane + 32], g_cs[0][b][lane + 32]);
#pragma unroll
        for (int off = 16; off; off >>= 1) {
            float m2 = __shfl_xor_sync(0xFFFFFFFFu, m, off);
            float s2 = __shfl_xor_sync(0xFFFFFFFFu, s, off);
            smx_comb(m, s, m2, s2);
        }
        if (lane == 0) { sM = m; sI = 1.f / s; }
    }
    __syncthreads();
    out_att[b * TT + l] = __expf(g_logit0[b][l] - sM) * sI;
}

// ---------------- kernel 5: fold pooled partials with global fixup --------
// pooled[i][b][d] = (1/(k_i * S)) * sum_c part[c][i][b][d] * exp(m_c - M)
__global__ void k_fold_pooled() {
    int idx = blockIdx.x * 256 + threadIdx.x;
    if (idx >= NLEV * BB * DD) return;
    int i = idx / (BB * DD);
    int b = (idx / DD) % BB;

    float M = BIG_NEG, S = 0.f;
#pragma unroll 8
    for (int c = 0; c < NCHK; c++) smx_comb(M, S, g_cm[i][b][c], g_cs[i][b][c]);
    float scl = (1.f / S) * (1.f / (float)(i + 1));

    float acc = 0.f;
#pragma unroll 8
    for (int c = 0; c < NCHK; c++) {
        float p = (&g_pooled_part[0][0][0][0])[(size_t)c * NLEV * BB * DD + idx];
        acc = fmaf(p, __expf(g_cm[i][b][c] - M), acc);
    }
    (&g_pooled[0][0][0])[idx] = acc * scl;
}

// ---------------- kernel 6: ctx partials = pooled_i @ Ww[i]^T -------------
__global__ void k_ctx(const float* __restrict__ Ww) {
    int i  = blockIdx.z;
    int e0 = blockIdx.y * 128;
    int dc = blockIdx.x;
    int d0 = dc * 64;

    __shared__ float tW[128 * 65];
    __shared__ float sp[BB * 64];

    for (int idx = threadIdx.x; idx < 128 * 64; idx += 128) {
        int r = idx >> 6, c = idx & 63;
        tW[r * 65 + c] = Ww[(size_t)i * DD * DD + (size_t)(e0 + r) * DD + d0 + c];
    }
    for (int idx = threadIdx.x; idx < BB * 64; idx += 128) {
        int bb = idx >> 6, cc = idx & 63;
        sp[idx] = g_pooled[i][bb][d0 + cc];
    }
    __syncthreads();

    float acc[BB];
#pragma unroll
    for (int b = 0; b < BB; b++) acc[b] = 0.f;

    for (int c = 0; c < 64; c++) {
        float w = tW[threadIdx.x * 65 + c];
#pragma unroll
        for (int b = 0; b < BB; b++) acc[b] = fmaf(w, sp[b * 64 + c], acc[b]);
    }
    int e = e0 + threadIdx.x;
#pragma unroll
    for (int b = 0; b < BB; b++) g_ctx_part[i][dc][b][e] = acc[b];
}

// ---------------- kernel 7: final ctx fold + bias -> d_out ----------------
__global__ void k_out(const float* __restrict__ Wb, float* __restrict__ out_ctx) {
    int idx = blockIdx.x * 256 + threadIdx.x;
    if (idx >= BB * DD) return;
    int e = idx % DD;
    float s = 0.f;
#pragma unroll
    for (int i = 0; i < NLEV; i++) {
#pragma unroll
        for (int ch = 0; ch < CTXCH; ch++)
            s += (&g_ctx_part[0][0][0][0])[((i * CTXCH + ch) * BB * DD) + idx];
        s += Wb[i * DD + e];
    }
    out_ctx[idx] = s;
}

// ---------------- launch ---------------------------------------------------
extern "C" void kernel_launch(void* const* d_in, const int* in_sizes, int n_in,
                              void* d_out, int out_size) {
    const float* s_prev = (const float*)d_in[0];
    const float* enc    = (const float*)d_in[1];
    const int*   mask   = (const int*)  d_in[2];
    const float* Vw     = (const float*)d_in[3];
    const float* Vb     = (const float*)d_in[4];
    const float* Ww     = (const float*)d_in[5];
    const float* Wb     = (const float*)d_in[6];

    float* out     = (float*)d_out;
    float* out_ctx = out;            // [B, D]
    float* out_att = out + BB * DD;  // [B, T]

    k_proj       <<<dim3(32, NLEV), 128>>>(s_prev, Vw, Vb);
    k_fold_u     <<<(NLEV * BB * DD + 255) / 256, 256>>>();
    k_nop        <<<1, 32>>>();   // aligns k_fused to the ncu-captured slot (#4)
    k_fused      <<<dim3(NCHK, BB), 128>>>(enc, mask);
    k_attout     <<<dim3(8, BB), 512>>>(out_att);
    k_fold_pooled<<<(NLEV * BB * DD + 255) / 256, 256>>>();
    k_ctx        <<<dim3(CTXCH, 4, NLEV), 128>>>(Ww);
    k_out        <<<(BB * DD + 255) / 256, 256>>>(Wb, out_ctx);
}

// round 17
// speedup vs baseline: 1.0753x; 1.0753x over previous
#include <cuda_runtime.h>
#include <math.h>

#define BB 16
#define TT 4096
#define DD 512
#define NLEV 3
#define NECH 8              // e-chunks in k_proj
#define TCH 64              // tokens per fused chunk
#define NCHK (TT/TCH)       // 64
#define CTXCH 8             // d-chunks in k_ctx
#define BIG_NEG (-1e30f)

typedef unsigned long long ull;

// one enc row = DD floats = 128 ulonglong2 (16B) elements
#define ROW_U2 ((DD * 4) / 16)
static_assert(ROW_U2 == 128, "row stride in ulonglong2 units must be 128");

__device__ __forceinline__ ull pk2(float lo, float hi) {
    ull r; asm("mov.b64 %0, {%1,%2};" : "=l"(r) : "f"(lo), "f"(hi)); return r;
}
__device__ __forceinline__ ull fma2(ull a, ull b, ull c) {
    ull d; asm("fma.rn.f32x2 %0, %1, %2, %3;" : "=l"(d) : "l"(a), "l"(b), "l"(c)); return d;
}
__device__ __forceinline__ ull add2(ull a, ull b) {
    ull d; asm("add.rn.f32x2 %0, %1, %2;" : "=l"(d) : "l"(a), "l"(b)); return d;
}
__device__ __forceinline__ float hsum2(ull v) {
    float x, y; asm("mov.b64 {%0,%1}, %2;" : "=f"(x), "=f"(y) : "l"(v)); return x + y;
}
__device__ __forceinline__ void upk2(ull v, float& x, float& y) {
    asm("mov.b64 {%0,%1}, %2;" : "=f"(x), "=f"(y) : "l"(v));
}
// online-softmax monoid combine
__device__ __forceinline__ void smx_comb(float& m, float& s, float m2, float s2) {
    float M = fmaxf(m, m2);
    s = s * __expf(m - M) + s2 * __expf(m2 - M);
    m = M;
}

// ---------------- device scratch (no allocations allowed) ----------------
__device__ __align__(16) float g_u_part[NECH][NLEV][BB][DD];
__device__ float g_c_part[NECH][NLEV][BB];
__device__ __align__(16) float g_u[NLEV][BB][DD];
__device__ float g_logit0[BB][TT];               // level-0 logits only (for att out)
__device__ float g_cm[NLEV][BB][NCHK];           // per-chunk normalizer (max incl boundaries)
__device__ float g_cs[NLEV][BB][NCHK];           // per-chunk sum rel. to g_cm
__device__ float g_cscale[NLEV][BB][NCHK];       // exp(m_c - M) / (S * k)  -- precomputed
__device__ __align__(16) float g_pooled_part[NCHK][NLEV][BB][DD];  // locally-scaled
__device__ __align__(16) float g_pooled[NLEV][BB][DD];
__device__ float g_ctx_part[NLEV][CTXCH][BB][DD];

// ---------------- kernel 1: u_i = s_prev @ Vw[i], c_i = s_prev . Vb[i] ----
__global__ void k_proj(const float* __restrict__ s_prev,
                       const float* __restrict__ Vw,
                       const float* __restrict__ Vb) {
    int i  = blockIdx.y;
    int dt = blockIdx.x & 3;
    int ec = blockIdx.x >> 2;
    int d  = dt * 128 + threadIdx.x;
    int e0 = ec * 64;

    __shared__ float sp[BB][64];
    for (int idx = threadIdx.x; idx < BB * 64; idx += 128) {
        int b = idx >> 6, e = idx & 63;
        sp[b][e] = s_prev[b * DD + e0 + e];
    }
    __syncthreads();

    float acc[BB];
#pragma unroll
    for (int b = 0; b < BB; b++) acc[b] = 0.f;

    const float* wp = Vw + (size_t)i * DD * DD + (size_t)e0 * DD + d;
#pragma unroll 4
    for (int e = 0; e < 64; e++) {
        float w = wp[(size_t)e * DD];
#pragma unroll
        for (int b = 0; b < BB; b++) acc[b] = fmaf(sp[b][e], w, acc[b]);
    }
#pragma unroll
    for (int b = 0; b < BB; b++) g_u_part[ec][i][b][d] = acc[b];

    if (dt == 0 && threadIdx.x < BB) {
        int b = threadIdx.x;
        float c = 0.f;
        for (int e = 0; e < 64; e++) c = fmaf(sp[b][e], Vb[i * DD + e0 + e], c);
        g_c_part[ec][i][b] = c;
    }
}

// ---------------- kernel 2: fold u partials -------------------------------
__global__ void k_fold_u() {
    int idx = blockIdx.x * 256 + threadIdx.x;
    if (idx < NLEV * BB * DD) {
        float s = 0.f;
#pragma unroll
        for (int p = 0; p < NECH; p++) s += (&g_u_part[0][0][0][0])[p * NLEV * BB * DD + idx];
        (&g_u[0][0][0])[idx] = s;
    }
}

// ---------------- profiling-alignment no-op (keeps k_fused in ncu slot) ---
__global__ void k_nop() {}

// ---------------- kernel 3: FULLY FUSED single-pass over enc --------------
// R15-proven version (no reg cap, 12 independent accumulators).
// grid (NCHK=64, B), 128 threads (4 warps). Per 64-token chunk:
//   phase 1: dots for t0-2..t0+65 (register-cached u, pair loop)
//   phase 2: logits (level-0 stored), chunk normalizer m' (max incl.
//            boundaries -> no inf), chunk sum, LOCAL pooling weights
//   phase 3: re-stream the SAME 128KB tile (L1/L2-hot)
__global__ void __launch_bounds__(128) k_fused(const float* __restrict__ enc,
                                               const int* __restrict__ mask) {
    int b    = blockIdx.y;
    int chnk = blockIdx.x;
    int t0   = chnk * TCH;
    int tid  = threadIdx.x, warp = tid >> 5, lane = tid & 31;

    __shared__ float sd[NLEV][68];     // dots, s = t - t0 + 2 in [0,68)
    __shared__ float slog[NLEV][66];   // logits, s in [0,66)
    __shared__ float sM[NLEV];
    __shared__ ull   sw[NLEV][TCH];    // packed local weights

    // register-cache u slices: lane owns ulonglong2 indices {lane+32q}
    ulonglong2 v0[4], v1[4], v2[4];
    {
        const ulonglong2* u0 = (const ulonglong2*)&g_u[0][b][0];
        const ulonglong2* u1 = (const ulonglong2*)&g_u[1][b][0];
        const ulonglong2* u2 = (const ulonglong2*)&g_u[2][b][0];
#pragma unroll
        for (int q = 0; q < 4; q++) {
            v0[q] = u0[lane + 32 * q];
            v1[q] = u1[lane + 32 * q];
            v2[q] = u2[lane + 32 * q];
        }
    }

    const ulonglong2* e2 = (const ulonglong2*)(enc + (size_t)b * TT * DD);

    // ---- phase 1: dots (pairs; warp w covers t0+16w..t0+16w+15) ----
    int  extra_t  = 0;
    bool has_x    = false;
    if (warp == 0 && t0 > 0)       { has_x = true; extra_t = t0 - 2; }
    if (warp == 1 && t0 + TCH < TT){ has_x = true; extra_t = t0 + TCH; }
    int npair = 8 + (has_x ? 1 : 0);

    for (int it = 0; it < npair; it++) {
        int tp = (it < 8) ? (t0 + warp * 16 + 2 * it) : extra_t;
        const ulonglong2* r0 = e2 + (size_t)tp * ROW_U2 + lane;
        const ulonglong2* r1 = e2 + (size_t)(tp + 1) * ROW_U2 + lane;

        ulonglong2 h0[4], h1[4];
#pragma unroll
        for (int q = 0; q < 4; q++) h0[q] = r0[32 * q];
#pragma unroll
        for (int q = 0; q < 4; q++) h1[q] = r1[32 * q];

        ull A0 = 0, B0 = 0, A1 = 0, B1 = 0, A2 = 0, B2 = 0;
        ull C0 = 0, D0 = 0, C1 = 0, D1 = 0, C2 = 0, D2 = 0;
#pragma unroll
        for (int q = 0; q < 4; q++) {
            A0 = fma2(h0[q].x, v0[q].x, A0); B0 = fma2(h0[q].y, v0[q].y, B0);
            A1 = fma2(h0[q].x, v1[q].x, A1); B1 = fma2(h0[q].y, v1[q].y, B1);
            A2 = fma2(h0[q].x, v2[q].x, A2); B2 = fma2(h0[q].y, v2[q].y, B2);
            C0 = fma2(h1[q].x, v0[q].x, C0); D0 = fma2(h1[q].y, v0[q].y, D0);
            C1 = fma2(h1[q].x, v1[q].x, C1); D1 = fma2(h1[q].y, v1[q].y, D1);
            C2 = fma2(h1[q].x, v2[q].x, C2); D2 = fma2(h1[q].y, v2[q].y, D2);
        }
        ull p0 = pk2(hsum2(A0) + hsum2(B0), hsum2(C0) + hsum2(D0));
        ull p1 = pk2(hsum2(A1) + hsum2(B1), hsum2(C1) + hsum2(D1));
        ull p2 = pk2(hsum2(A2) + hsum2(B2), hsum2(C2) + hsum2(D2));

#pragma unroll
        for (int off = 16; off; off >>= 1) {
            p0 = add2(p0, __shfl_down_sync(0xFFFFFFFFu, p0, off));
            p1 = add2(p1, __shfl_down_sync(0xFFFFFFFFu, p1, off));
            p2 = add2(p2, __shfl_down_sync(0xFFFFFFFFu, p2, off));
        }
        if (lane == 0) {
            int s0 = tp - t0 + 2;
            float x, y;
            upk2(p0, x, y); sd[0][s0] = x; sd[0][s0 + 1] = y;
            upk2(p1, x, y); sd[1][s0] = x; sd[1][s0 + 1] = y;
            upk2(p2, x, y); sd[2][s0] = x; sd[2][s0 + 1] = y;
        }
    }
    __syncthreads();

    // ---- phase 2a: logits (s = 0..65, l = t0-2+s); store only level 0 ----
    const int* mp = mask + b * TT;
    for (int idx = tid; idx < NLEV * 66; idx += 128) {
        int i = idx / 66, s = idx % 66;
        int l = t0 - 2 + s;
        int L = TT - i;
        float v = BIG_NEG;
        if (l >= 0 && l < L) {
            float ws = sd[i][s];
            bool  mk = (mp[l] != 0);
            if (i >= 1) { ws += sd[i][s + 1]; mk = mk || (mp[l + 1] != 0); }
            if (i == 2) { ws += sd[i][s + 2]; mk = mk || (mp[l + 2] != 0); }
            if (!mk) {
                float cst = 0.f;
#pragma unroll
                for (int p = 0; p < NECH; p++) cst += g_c_part[p][i][b];
                v = ws * (1.f / (float)(i + 1)) + cst;
            }
        }
        slog[i][s] = v;
        if (i == 0 && s >= 2) g_logit0[b][l] = v;
    }
    __syncthreads();

    // ---- phase 2b: chunk normalizer + sum (warp i = level i) ----
    if (warp < NLEV) {
        float a  = slog[warp][2 + lane];
        float bv = slog[warp][34 + lane];
        float m  = fmaxf(a, bv);
        if (lane < 2) m = fmaxf(m, slog[warp][lane]);   // boundary positions
#pragma unroll
        for (int off = 16; off; off >>= 1)
            m = fmaxf(m, __shfl_xor_sync(0xFFFFFFFFu, m, off));
        float s = __expf(a - m) + __expf(bv - m);
#pragma unroll
        for (int off = 16; off; off >>= 1)
            s += __shfl_xor_sync(0xFFFFFFFFu, s, off);
        if (lane == 0) {
            sM[warp] = m;
            g_cm[warp][b][chnk] = m;
            g_cs[warp][b][chnk] = s;
        }
    }
    __syncthreads();

    // ---- phase 2c: local pooling weights (chunk-normalized; args <= 0) ----
    for (int idx = tid; idx < NLEV * TCH; idx += 128) {
        int i = idx / TCH, j = idx % TCH, s = j + 2;
        float M = sM[i];
        float w = __expf(slog[i][s] - M);
        if (i >= 1) w += __expf(slog[i][s - 1] - M);
        if (i == 2) w += __expf(slog[i][s - 2] - M);
        sw[i][j] = pk2(w, w);
    }
    __syncthreads();

    // ---- phase 3: re-stream the tile (L1/L2-hot) ----
    const ulonglong2* base = e2 + (size_t)t0 * ROW_U2 + tid;
    ull a0x = 0, a0y = 0, a1x = 0, a1y = 0, a2x = 0, a2y = 0;

#pragma unroll 16
    for (int j = 0; j < TCH; j++) {
        ulonglong2 h = base[(size_t)j * ROW_U2];
        ull w0 = sw[0][j], w1 = sw[1][j], w2 = sw[2][j];
        a0x = fma2(w0, h.x, a0x); a0y = fma2(w0, h.y, a0y);
        a1x = fma2(w1, h.x, a1x); a1y = fma2(w1, h.y, a1y);
        a2x = fma2(w2, h.x, a2x); a2y = fma2(w2, h.y, a2y);
    }
    ulonglong2 r0; r0.x = a0x; r0.y = a0y;
    ulonglong2 r1; r1.x = a1x; r1.y = a1y;
    ulonglong2 r2; r2.x = a2x; r2.y = a2y;
    ((ulonglong2*)&g_pooled_part[chnk][0][b][0])[tid] = r0;
    ((ulonglong2*)&g_pooled_part[chnk][1][b][0])[tid] = r1;
    ((ulonglong2*)&g_pooled_part[chnk][2][b][0])[tid] = r2;
}

// ---------------- kernel 4: att output (level 0) --------------------------
__global__ void k_attout(float* __restrict__ out_att) {
    int b = blockIdx.y;
    int l = blockIdx.x * 512 + threadIdx.x;
    int warp = threadIdx.x >> 5, lane = threadIdx.x & 31;

    __shared__ float sM, sI;
    if (warp == 0) {
        float m = g_cm[0][b][lane], s = g_cs[0][b][lane];
        smx_comb(m, s, g_cm[0][b][lane + 32], g_cs[0][b][lane + 32]);
#pragma unroll
        for (int off = 16; off; off >>= 1) {
            float m2 = __shfl_xor_sync(0xFFFFFFFFu, m, off);
            float s2 = __shfl_xor_sync(0xFFFFFFFFu, s, off);
            smx_comb(m, s, m2, s2);
        }
        if (lane == 0) { sM = m; sI = 1.f / s; }
    }
    __syncthreads();
    out_att[b * TT + l] = __expf(g_logit0[b][l] - sM) * sI;
}

// ---------------- kernel 4b: per-chunk scale factors (once per (i,b)) -----
// grid (NLEV, BB), 32 threads. scale[c] = exp(m_c - M) / (S * k)
__global__ void k_scale() {
    int i = blockIdx.x, b = blockIdx.y;
    int lane = threadIdx.x;

    float m = g_cm[i][b][lane], s = g_cs[i][b][lane];
    smx_comb(m, s, g_cm[i][b][lane + 32], g_cs[i][b][lane + 32]);
#pragma unroll
    for (int off = 16; off; off >>= 1) {
        float m2 = __shfl_xor_sync(0xFFFFFFFFu, m, off);
        float s2 = __shfl_xor_sync(0xFFFFFFFFu, s, off);
        smx_comb(m, s, m2, s2);
    }
    // all lanes now hold global (M, S)
    float scl = (1.f / s) * (1.f / (float)(i + 1));
    g_cscale[i][b][lane]      = __expf(g_cm[i][b][lane]      - m) * scl;
    g_cscale[i][b][lane + 32] = __expf(g_cm[i][b][lane + 32] - m) * scl;
}

// ---------------- kernel 5: fold pooled partials (pure weighted sum) ------
__global__ void k_fold_pooled() {
    int idx = blockIdx.x * 256 + threadIdx.x;
    if (idx >= NLEV * BB * DD) return;
    int i = idx / (BB * DD);
    int b = (idx / DD) % BB;

    const float* sc = &g_cscale[i][b][0];
    float acc = 0.f;
#pragma unroll 8
    for (int c = 0; c < NCHK; c++) {
        float p = (&g_pooled_part[0][0][0][0])[(size_t)c * NLEV * BB * DD + idx];
        acc = fmaf(p, sc[c], acc);
    }
    (&g_pooled[0][0][0])[idx] = acc;
}

// ---------------- kernel 6: ctx partials = pooled_i @ Ww[i]^T -------------
__global__ void k_ctx(const float* __restrict__ Ww) {
    int i  = blockIdx.z;
    int e0 = blockIdx.y * 128;
    int dc = blockIdx.x;
    int d0 = dc * 64;

    __shared__ float tW[128 * 65];
    __shared__ float sp[BB * 64];

    for (int idx = threadIdx.x; idx < 128 * 64; idx += 128) {
        int r = idx >> 6, c = idx & 63;
        tW[r * 65 + c] = Ww[(size_t)i * DD * DD + (size_t)(e0 + r) * DD + d0 + c];
    }
    for (int idx = threadIdx.x; idx < BB * 64; idx += 128) {
        int bb = idx >> 6, cc = idx & 63;
        sp[idx] = g_pooled[i][bb][d0 + cc];
    }
    __syncthreads();

    float acc[BB];
#pragma unroll
    for (int b = 0; b < BB; b++) acc[b] = 0.f;

    for (int c = 0; c < 64; c++) {
        float w = tW[threadIdx.x * 65 + c];
#pragma unroll
        for (int b = 0; b < BB; b++) acc[b] = fmaf(w, sp[b * 64 + c], acc[b]);
    }
    int e = e0 + threadIdx.x;
#pragma unroll
    for (int b = 0; b < BB; b++) g_ctx_part[i][dc][b][e] = acc[b];
}

// ---------------- kernel 7: final ctx fold + bias -> d_out ----------------
__global__ void k_out(const float* __restrict__ Wb, float* __restrict__ out_ctx) {
    int idx = blockIdx.x * 256 + threadIdx.x;
    if (idx >= BB * DD) return;
    int e = idx % DD;
    float s = 0.f;
#pragma unroll
    for (int i = 0; i < NLEV; i++) {
#pragma unroll
        for (int ch = 0; ch < CTXCH; ch++)
            s += (&g_ctx_part[0][0][0][0])[((i * CTXCH + ch) * BB * DD) + idx];
        s += Wb[i * DD + e];
    }
    out_ctx[idx] = s;
}

// ---------------- launch ---------------------------------------------------
extern "C" void kernel_launch(void* const* d_in, const int* in_sizes, int n_in,
                              void* d_out, int out_size) {
    const float* s_prev = (const float*)d_in[0];
    const float* enc    = (const float*)d_in[1];
    const int*   mask   = (const int*)  d_in[2];
    const float* Vw     = (const float*)d_in[3];
    const float* Vb     = (const float*)d_in[4];
    const float* Ww     = (const float*)d_in[5];
    const float* Wb     = (const float*)d_in[6];

    float* out     = (float*)d_out;
    float* out_ctx = out;            // [B, D]
    float* out_att = out + BB * DD;  // [B, T]

    k_proj       <<<dim3(32, NLEV), 128>>>(s_prev, Vw, Vb);
    k_fold_u     <<<(NLEV * BB * DD + 255) / 256, 256>>>();
    k_nop        <<<1, 32>>>();   // aligns k_fused to the ncu-captured slot (#4)
    k_fused      <<<dim3(NCHK, BB), 128>>>(enc, mask);
    k_scale      <<<dim3(NLEV, BB), 32>>>();
    k_attout     <<<dim3(8, BB), 512>>>(out_att);
    k_fold_pooled<<<(NLEV * BB * DD + 255) / 256, 256>>>();
    k_ctx        <<<dim3(CTXCH, 4, NLEV), 128>>>(Ww);
    k_out        <<<(BB * DD + 255) / 256, 256>>>(Wb, out_ctx);
}